// round 10
// baseline (speedup 1.0000x reference)
#include <cuda_runtime.h>
#include <cuda_bf16.h>
#include <math.h>

#define N_ENTITY 64368
#define N_REL    46
#define NBASES   8
#define DDIM     128
#define E_EDGES  600000
#define B_USERS  64
#define L_CTX    50
#define NE_ENT   256

#define NCAND    (B_USERS * L_CTX + NE_ENT)   // 3456 candidate ids
#define MMAX     4096                          // > NCAND

// ---- device-global scratch (allocation forbidden; int atomics only) ----
__device__ int   g_slot[N_ENTITY];         // entity -> compact slot (-1 if unused)
__device__ int   g_ent[MMAX];              // slot -> entity
__device__ int   g_M;                      // number of used slots
__device__ int   g_ne;                     // number of relevant edges
__device__ int2  g_clist[E_EDGES];         // compact unsorted relevant edges {slot, src|rel<<17}
__device__ int   g_eoff[MMAX + 1];         // slot-sorted edge offsets
__device__ int   g_deg2[MMAX * N_REL];     // per-(slot,rel) degree
__device__ int   g_elist[E_EDGES];         // slot-sorted edges: src | (rel<<17)
__device__ __align__(16) float g_kgc[MMAX * DDIM];  // 2 MB compact kg_emb
__device__ float g_sent[MMAX];             // per-slot attention score

// ---------------------------------------------------------------------------
// setup: slot = -1, counters = 0
// ---------------------------------------------------------------------------
__global__ void k_setup() {
    const int stride = gridDim.x * blockDim.x;
    const int tid = blockIdx.x * blockDim.x + threadIdx.x;
    for (int i = tid; i < N_ENTITY; i += stride) g_slot[i] = -1;
    if (tid == 0) { g_M = 0; g_ne = 0; }
}

// ---------------------------------------------------------------------------
// assign compact slots to candidate entities (CAS dedup; order-free).
// claimer also zeroes its slot's degree row (only claimed rows are read later).
// ---------------------------------------------------------------------------
__global__ void k_assign(const int* __restrict__ ctx, const int* __restrict__ entity_ids) {
    int t = blockIdx.x * blockDim.x + threadIdx.x;
    if (t >= NCAND) return;
    int id = (t < B_USERS * L_CTX) ? ctx[t] : entity_ids[t - B_USERS * L_CTX];
    if (atomicCAS(&g_slot[id], -1, -2) == -1) {
        int s = atomicAdd(&g_M, 1);
        g_ent[s] = id;
#pragma unroll
        for (int r = 0; r < N_REL; r++) g_deg2[s * N_REL + r] = 0;
        g_slot[id] = s;                 // publish after deg row is zeroed
    }
}

// ---------------------------------------------------------------------------
// SINGLE edge pass: degree atomic + compact append of relevant edges
// ---------------------------------------------------------------------------
__global__ void k_epass(const int* __restrict__ edge_index, const int* __restrict__ edge_type) {
    int e = blockIdx.x * blockDim.x + threadIdx.x;
    if (e >= E_EDGES) return;
    int dst = edge_index[E_EDGES + e];
    int s = g_slot[dst];
    if (s < 0) return;
    int rel = edge_type[e];
    int src = edge_index[e];
    atomicAdd(&g_deg2[s * N_REL + rel], 1);
    int p = atomicAdd(&g_ne, 1);
    g_clist[p] = make_int2(s, src | (rel << 17));   // src < 2^17, rel < 2^6
}

// ---------------------------------------------------------------------------
// counting sort of the compact list by slot: smem hist -> scan -> scatter.
// single block, 1024 threads; n is ~32K for this dataset (correct for any n).
// ---------------------------------------------------------------------------
__global__ void __launch_bounds__(1024) k_csort() {
    __shared__ int sh_hist[MMAX];       // 16 KB
    __shared__ int sh_cur[MMAX];        // 16 KB
    __shared__ int wsum[32];
    int t = threadIdx.x, lane = t & 31, wid = t >> 5;
    int n = g_ne;

#pragma unroll
    for (int j = 0; j < MMAX / 1024; j++) sh_hist[t + j * 1024] = 0;
    __syncthreads();

    for (int i = t; i < n; i += 1024)
        atomicAdd(&sh_hist[g_clist[i].x], 1);
    __syncthreads();

    // exclusive scan of 4096 bins: 4 per thread, warp scan, block scan
    int v[4]; int sum = 0;
#pragma unroll
    for (int j = 0; j < 4; j++) { v[j] = sh_hist[t * 4 + j]; sum += v[j]; }
    int s = sum;
#pragma unroll
    for (int o = 1; o < 32; o <<= 1) {
        int a = __shfl_up_sync(0xFFFFFFFFu, s, o);
        if (lane >= o) s += a;
    }
    if (lane == 31) wsum[wid] = s;
    __syncthreads();
    if (wid == 0) {
        int ws = wsum[lane];
#pragma unroll
        for (int o = 1; o < 32; o <<= 1) {
            int a = __shfl_up_sync(0xFFFFFFFFu, ws, o);
            if (lane >= o) ws += a;
        }
        wsum[lane] = ws;
    }
    __syncthreads();
    int base = ((wid > 0) ? wsum[wid - 1] : 0) + s - sum;
#pragma unroll
    for (int j = 0; j < 4; j++) {
        g_eoff[t * 4 + j] = base;
        sh_cur[t * 4 + j] = base;
        base += v[j];
    }
    if (t == 1023) g_eoff[MMAX] = base;
    __syncthreads();

    // scatter
    for (int i = t; i < n; i += 1024) {
        int2 e = g_clist[i];
        int pos = atomicAdd(&sh_cur[e.x], 1);
        g_elist[pos] = e.y;
    }
}

// ---------------------------------------------------------------------------
// aggregation: warp per needed slot; gather basis rows directly.
// kg = root + bias + sum_edges norm * sum_b comp[rel,b] * basis[b][src]
// ---------------------------------------------------------------------------
__global__ void __launch_bounds__(256) k_agg(const float* __restrict__ basis,
                                             const float* __restrict__ comp,
                                             const float* __restrict__ root,
                                             const float* __restrict__ bias) {
    __shared__ float s_comp[N_REL * NBASES];
    for (int i = threadIdx.x; i < N_REL * NBASES; i += blockDim.x) s_comp[i] = comp[i];
    __syncthreads();

    int slot = (blockIdx.x * blockDim.x + threadIdx.x) >> 5;
    int lane = threadIdx.x & 31;
    if (slot >= g_M) return;

    int ent = g_ent[slot];
    float4 acc = reinterpret_cast<const float4*>(root)[(size_t)ent * 32 + lane];
    float4 bv  = reinterpret_cast<const float4*>(bias)[lane];
    acc.x += bv.x; acc.y += bv.y; acc.z += bv.z; acc.w += bv.w;

    int n0 = g_eoff[slot], n1 = g_eoff[slot + 1];
    for (int i = n0; i < n1; i++) {
        int packed = g_elist[i];                 // warp-broadcast load
        int src = packed & 0x1FFFF;
        int rel = packed >> 17;
        float norm = 1.0f / (float)max(g_deg2[slot * N_REL + rel], 1);
        const float* c = s_comp + rel * NBASES;
        const float4* bp = reinterpret_cast<const float4*>(basis) + (size_t)src * 32 + lane;
        float4 br[NBASES];
#pragma unroll
        for (int b = 0; b < NBASES; b++) br[b] = bp[(size_t)b * (N_ENTITY * 32)];
        float4 m;
        m.x = c[0] * br[0].x; m.y = c[0] * br[0].y; m.z = c[0] * br[0].z; m.w = c[0] * br[0].w;
#pragma unroll
        for (int b = 1; b < NBASES; b++) {
            float cb = c[b];
            m.x += cb * br[b].x; m.y += cb * br[b].y; m.z += cb * br[b].z; m.w += cb * br[b].w;
        }
        acc.x += norm * m.x; acc.y += norm * m.y; acc.z += norm * m.z; acc.w += norm * m.w;
    }
    reinterpret_cast<float4*>(g_kgc)[(size_t)slot * 32 + lane] = acc;
}

// ---------------------------------------------------------------------------
// per-slot attention score; attn_W staged through smem in 32-row tiles.
// block = 8 warps, each warp owns one slot.
// ---------------------------------------------------------------------------
#define SC_WARPS 8
__global__ void __launch_bounds__(SC_WARPS * 32) k_score(const float* __restrict__ attn_W,
                                                         const float* __restrict__ attn_b) {
    __shared__ float sW[32 * DDIM];     // 16 KB tile
    int t = threadIdx.x;
    int lane = t & 31, wid = t >> 5;
    int slot = blockIdx.x * SC_WARPS + wid;
    bool active = slot < g_M;

    float4 h4 = make_float4(0.f, 0.f, 0.f, 0.f);
    if (active)
        h4 = reinterpret_cast<const float4*>(g_kgc + (size_t)slot * DDIM)[lane];

    float u0 = 0.f, u1 = 0.f, u2 = 0.f, u3 = 0.f;
#pragma unroll
    for (int tile = 0; tile < DDIM / 32; tile++) {
        __syncthreads();
        for (int i = t; i < 32 * DDIM; i += SC_WARPS * 32)
            sW[i] = attn_W[tile * 32 * DDIM + i];
        __syncthreads();
#pragma unroll 4
        for (int kk = 0; kk < 32; kk++) {
            int k = tile * 32 + kk;
            int sl = k >> 2, cp = k & 3;
            float hv = (cp == 0) ? h4.x : (cp == 1) ? h4.y : (cp == 2) ? h4.z : h4.w;
            float hk = __shfl_sync(0xFFFFFFFFu, hv, sl);
            const float* wr = sW + kk * DDIM;
            u0 += hk * wr[lane];
            u1 += hk * wr[lane + 32];
            u2 += hk * wr[lane + 64];
            u3 += hk * wr[lane + 96];
        }
    }
    if (active) {
        float acc = tanhf(u0) * attn_b[lane] + tanhf(u1) * attn_b[lane + 32]
                  + tanhf(u2) * attn_b[lane + 64] + tanhf(u3) * attn_b[lane + 96];
#pragma unroll
        for (int o = 16; o; o >>= 1) acc += __shfl_xor_sync(0xFFFFFFFFu, acc, o);
        if (lane == 0) g_sent[slot] = acc;
    }
}

// ---------------------------------------------------------------------------
// fused output kernel: blocks [0,64) = users, [64,320) = entities
// ---------------------------------------------------------------------------
__global__ void __launch_bounds__(DDIM) k_out(const int* __restrict__ ctx,
                       const int* __restrict__ cmask,
                       const int* __restrict__ entity_ids,
                       const float* __restrict__ fc1_W, const float* __restrict__ fc1_b,
                       const float* __restrict__ fc2_W, const float* __restrict__ fc2_b,
                       const float* __restrict__ efc1_W, const float* __restrict__ efc1_b,
                       const float* __restrict__ efc2_W, const float* __restrict__ efc2_b,
                       float* __restrict__ out) {
    __shared__ float xin[DDIM];
    __shared__ float yv[DDIM];
    __shared__ float attn[L_CTX];
    int t = threadIdx.x;

    const float *W1, *b1, *W2, *b2;
    float* dst;

    if (blockIdx.x < B_USERS) {
        int b = blockIdx.x;
        if (t == 0) {
            float mx = -3.4e38f; bool any = false;
            float scl[L_CTX];
            for (int l = 0; l < L_CTX; l++) {
                scl[l] = g_sent[g_slot[ctx[b * L_CTX + l]]];
                if (cmask[b * L_CTX + l]) { any = true; mx = fmaxf(mx, scl[l]); }
            }
            float s = 0.f;
            for (int l = 0; l < L_CTX; l++) {
                float v = cmask[b * L_CTX + l] ? expf(scl[l] - mx) : 0.f;
                attn[l] = v; s += v;
            }
            float inv = any ? 1.f / s : 0.f;
            for (int l = 0; l < L_CTX; l++) attn[l] *= inv;
        }
        __syncthreads();
        // L_CTX = 50 is even: the pair loop covers all l (no tail)
        float r0 = 0.f, r1 = 0.f;
        for (int l = 0; l < L_CTX; l += 2) {
            int s0 = g_slot[ctx[b * L_CTX + l]];
            int s1 = g_slot[ctx[b * L_CTX + l + 1]];
            r0 += attn[l]     * g_kgc[(size_t)s0 * DDIM + t];
            r1 += attn[l + 1] * g_kgc[(size_t)s1 * DDIM + t];
        }
        xin[t] = r0 + r1;
        W1 = fc1_W; b1 = fc1_b; W2 = fc2_W; b2 = fc2_b;
        dst = out + b * DDIM;
    } else {
        int i = blockIdx.x - B_USERS;
        int slot = g_slot[entity_ids[i]];
        xin[t] = g_kgc[(size_t)slot * DDIM + t];
        W1 = efc1_W; b1 = efc1_b; W2 = efc2_W; b2 = efc2_b;
        dst = out + B_USERS * DDIM + i * DDIM;
    }
    __syncthreads();

    float y0 = 0.f, y1 = 0.f, y2 = 0.f, y3 = 0.f;
#pragma unroll 4
    for (int k = 0; k < DDIM; k += 4) {
        y0 += xin[k]     * W1[(k)     * DDIM + t];
        y1 += xin[k + 1] * W1[(k + 1) * DDIM + t];
        y2 += xin[k + 2] * W1[(k + 2) * DDIM + t];
        y3 += xin[k + 3] * W1[(k + 3) * DDIM + t];
    }
    yv[t] = fmaxf(b1[t] + (y0 + y1) + (y2 + y3), 0.f);
    __syncthreads();

    float o0 = 0.f, o1 = 0.f, o2 = 0.f, o3 = 0.f;
#pragma unroll 4
    for (int k = 0; k < DDIM; k += 4) {
        o0 += yv[k]     * W2[(k)     * DDIM + t];
        o1 += yv[k + 1] * W2[(k + 1) * DDIM + t];
        o2 += yv[k + 2] * W2[(k + 2) * DDIM + t];
        o3 += yv[k + 3] * W2[(k + 3) * DDIM + t];
    }
    dst[t] = b2[t] + (o0 + o1) + (o2 + o3);
}

// ---------------------------------------------------------------------------
extern "C" void kernel_launch(void* const* d_in, const int* in_sizes, int n_in,
                              void* d_out, int out_size) {
    const int*   edge_index = (const int*)d_in[0];
    const int*   edge_type  = (const int*)d_in[1];
    const int*   ctx        = (const int*)d_in[2];
    const int*   cmask      = (const int*)d_in[3];
    const int*   entity_ids = (const int*)d_in[4];
    const float* comp       = (const float*)d_in[5];
    const float* basis      = (const float*)d_in[6];
    const float* root       = (const float*)d_in[7];
    const float* bias       = (const float*)d_in[8];
    const float* attn_W     = (const float*)d_in[9];
    const float* attn_b     = (const float*)d_in[10];
    const float* fc1_W      = (const float*)d_in[11];
    const float* fc1_b      = (const float*)d_in[12];
    const float* fc2_W      = (const float*)d_in[13];
    const float* fc2_b      = (const float*)d_in[14];
    const float* efc1_W     = (const float*)d_in[15];
    const float* efc1_b     = (const float*)d_in[16];
    const float* efc2_W     = (const float*)d_in[17];
    const float* efc2_b     = (const float*)d_in[18];
    float* out = (float*)d_out;

    k_setup<<<128, 256>>>();
    k_assign<<<(NCAND + 255) / 256, 256>>>(ctx, entity_ids);
    k_epass<<<(E_EDGES + 255) / 256, 256>>>(edge_index, edge_type);
    k_csort<<<1, 1024>>>();
    k_agg<<<(MMAX * 32) / 256, 256>>>(basis, comp, root, bias);
    k_score<<<MMAX / SC_WARPS, SC_WARPS * 32>>>(attn_W, attn_b);
    k_out<<<B_USERS + NE_ENT, DDIM>>>(ctx, cmask, entity_ids,
                                      fc1_W, fc1_b, fc2_W, fc2_b,
                                      efc1_W, efc1_b, efc2_W, efc2_b, out);
}

// round 11
// speedup vs baseline: 1.0164x; 1.0164x over previous
#include <cuda_runtime.h>
#include <cuda_bf16.h>
#include <math.h>

#define N_ENTITY 64368
#define N_REL    46
#define NBASES   8
#define DDIM     128
#define E_EDGES  600000
#define B_USERS  64
#define L_CTX    50
#define NE_ENT   256

#define NCAND    (B_USERS * L_CTX + NE_ENT)   // 3456 candidate ids
#define MMAX     4096                          // > NCAND

// ---- device-global scratch (allocation forbidden; int atomics only) ----
__device__ int   g_slot[N_ENTITY];         // entity -> compact slot (-1 if unused)
__device__ int   g_ent[MMAX];              // slot -> entity
__device__ int   g_M;                      // number of used slots
__device__ int   g_ne;                     // number of relevant edges
__device__ int2  g_clist[E_EDGES];         // compact unsorted relevant edges {slot, src|rel<<17}
__device__ int   g_eoff[MMAX + 1];         // slot-sorted edge offsets
__device__ int   g_deg2[MMAX * N_REL];     // per-(slot,rel) degree
__device__ int   g_elist[E_EDGES];         // slot-sorted edges: src | (rel<<17)
__device__ __align__(16) float g_kgc[MMAX * DDIM];  // 2 MB compact kg_emb
__device__ float g_sent[MMAX];             // per-slot attention score

// ---------------------------------------------------------------------------
// setup: slot = -1, counters = 0
// ---------------------------------------------------------------------------
__global__ void k_setup() {
    const int stride = gridDim.x * blockDim.x;
    const int tid = blockIdx.x * blockDim.x + threadIdx.x;
    for (int i = tid; i < N_ENTITY; i += stride) g_slot[i] = -1;
    if (tid == 0) { g_M = 0; g_ne = 0; }
}

// ---------------------------------------------------------------------------
// assign compact slots to candidate entities (CAS dedup; order-free).
// claimer also zeroes its slot's degree row (only claimed rows are read later).
// ---------------------------------------------------------------------------
__global__ void k_assign(const int* __restrict__ ctx, const int* __restrict__ entity_ids) {
    int t = blockIdx.x * blockDim.x + threadIdx.x;
    if (t >= NCAND) return;
    int id = (t < B_USERS * L_CTX) ? ctx[t] : entity_ids[t - B_USERS * L_CTX];
    if (atomicCAS(&g_slot[id], -1, -2) == -1) {
        int s = atomicAdd(&g_M, 1);
        g_ent[s] = id;
#pragma unroll
        for (int r = 0; r < N_REL; r++) g_deg2[s * N_REL + r] = 0;
        g_slot[id] = s;                 // publish after deg row is zeroed
    }
}

// ---------------------------------------------------------------------------
// SINGLE edge pass: degree atomic + compact append of relevant edges
// ---------------------------------------------------------------------------
__global__ void k_epass(const int* __restrict__ edge_index, const int* __restrict__ edge_type) {
    int e = blockIdx.x * blockDim.x + threadIdx.x;
    if (e >= E_EDGES) return;
    int dst = edge_index[E_EDGES + e];
    int s = g_slot[dst];
    if (s < 0) return;
    int rel = edge_type[e];
    int src = edge_index[e];
    atomicAdd(&g_deg2[s * N_REL + rel], 1);
    int p = atomicAdd(&g_ne, 1);
    g_clist[p] = make_int2(s, src | (rel << 17));   // src < 2^17, rel < 2^6
}

// ---------------------------------------------------------------------------
// counting sort of the compact list by slot: smem hist -> scan -> scatter.
// single block, 1024 threads; n is ~32K for this dataset (correct for any n).
// ---------------------------------------------------------------------------
__global__ void __launch_bounds__(1024) k_csort() {
    __shared__ int sh_hist[MMAX];       // 16 KB
    __shared__ int sh_cur[MMAX];        // 16 KB
    __shared__ int wsum[32];
    int t = threadIdx.x, lane = t & 31, wid = t >> 5;
    int n = g_ne;

#pragma unroll
    for (int j = 0; j < MMAX / 1024; j++) sh_hist[t + j * 1024] = 0;
    __syncthreads();

    for (int i = t; i < n; i += 1024)
        atomicAdd(&sh_hist[g_clist[i].x], 1);
    __syncthreads();

    // exclusive scan of 4096 bins: 4 per thread, warp scan, block scan
    int v[4]; int sum = 0;
#pragma unroll
    for (int j = 0; j < 4; j++) { v[j] = sh_hist[t * 4 + j]; sum += v[j]; }
    int s = sum;
#pragma unroll
    for (int o = 1; o < 32; o <<= 1) {
        int a = __shfl_up_sync(0xFFFFFFFFu, s, o);
        if (lane >= o) s += a;
    }
    if (lane == 31) wsum[wid] = s;
    __syncthreads();
    if (wid == 0) {
        int ws = wsum[lane];
#pragma unroll
        for (int o = 1; o < 32; o <<= 1) {
            int a = __shfl_up_sync(0xFFFFFFFFu, ws, o);
            if (lane >= o) ws += a;
        }
        wsum[lane] = ws;
    }
    __syncthreads();
    int base = ((wid > 0) ? wsum[wid - 1] : 0) + s - sum;
#pragma unroll
    for (int j = 0; j < 4; j++) {
        g_eoff[t * 4 + j] = base;
        sh_cur[t * 4 + j] = base;
        base += v[j];
    }
    if (t == 1023) g_eoff[MMAX] = base;
    __syncthreads();

    // scatter
    for (int i = t; i < n; i += 1024) {
        int2 e = g_clist[i];
        int pos = atomicAdd(&sh_cur[e.x], 1);
        g_elist[pos] = e.y;
    }
}

// ---------------------------------------------------------------------------
// aggregation: warp per needed slot; gather basis rows directly.
// kg = root + bias + sum_edges norm * sum_b comp[rel,b] * basis[b][src]
// ---------------------------------------------------------------------------
__global__ void __launch_bounds__(256) k_agg(const float* __restrict__ basis,
                                             const float* __restrict__ comp,
                                             const float* __restrict__ root,
                                             const float* __restrict__ bias) {
    __shared__ float s_comp[N_REL * NBASES];
    for (int i = threadIdx.x; i < N_REL * NBASES; i += blockDim.x) s_comp[i] = comp[i];
    __syncthreads();

    int slot = (blockIdx.x * blockDim.x + threadIdx.x) >> 5;
    int lane = threadIdx.x & 31;
    if (slot >= g_M) return;

    int ent = g_ent[slot];
    float4 acc = reinterpret_cast<const float4*>(root)[(size_t)ent * 32 + lane];
    float4 bv  = reinterpret_cast<const float4*>(bias)[lane];
    acc.x += bv.x; acc.y += bv.y; acc.z += bv.z; acc.w += bv.w;

    int n0 = g_eoff[slot], n1 = g_eoff[slot + 1];
    for (int i = n0; i < n1; i++) {
        int packed = g_elist[i];                 // warp-broadcast load
        int src = packed & 0x1FFFF;
        int rel = packed >> 17;
        float norm = 1.0f / (float)max(g_deg2[slot * N_REL + rel], 1);
        const float* c = s_comp + rel * NBASES;
        const float4* bp = reinterpret_cast<const float4*>(basis) + (size_t)src * 32 + lane;
        float4 br[NBASES];
#pragma unroll
        for (int b = 0; b < NBASES; b++) br[b] = bp[(size_t)b * (N_ENTITY * 32)];
        float4 m;
        m.x = c[0] * br[0].x; m.y = c[0] * br[0].y; m.z = c[0] * br[0].z; m.w = c[0] * br[0].w;
#pragma unroll
        for (int b = 1; b < NBASES; b++) {
            float cb = c[b];
            m.x += cb * br[b].x; m.y += cb * br[b].y; m.z += cb * br[b].z; m.w += cb * br[b].w;
        }
        acc.x += norm * m.x; acc.y += norm * m.y; acc.z += norm * m.z; acc.w += norm * m.w;
    }
    reinterpret_cast<float4*>(g_kgc)[(size_t)slot * 32 + lane] = acc;
}

// ---------------------------------------------------------------------------
// per-slot attention score; attn_W staged through smem in 32-row tiles.
// block = 8 warps, each warp owns one slot.
// ---------------------------------------------------------------------------
#define SC_WARPS 8
__global__ void __launch_bounds__(SC_WARPS * 32) k_score(const float* __restrict__ attn_W,
                                                         const float* __restrict__ attn_b) {
    __shared__ float sW[32 * DDIM];     // 16 KB tile
    int t = threadIdx.x;
    int lane = t & 31, wid = t >> 5;
    int slot = blockIdx.x * SC_WARPS + wid;
    bool active = slot < g_M;

    float4 h4 = make_float4(0.f, 0.f, 0.f, 0.f);
    if (active)
        h4 = reinterpret_cast<const float4*>(g_kgc + (size_t)slot * DDIM)[lane];

    float u0 = 0.f, u1 = 0.f, u2 = 0.f, u3 = 0.f;
#pragma unroll
    for (int tile = 0; tile < DDIM / 32; tile++) {
        __syncthreads();
        for (int i = t; i < 32 * DDIM; i += SC_WARPS * 32)
            sW[i] = attn_W[tile * 32 * DDIM + i];
        __syncthreads();
#pragma unroll 4
        for (int kk = 0; kk < 32; kk++) {
            int k = tile * 32 + kk;
            int sl = k >> 2, cp = k & 3;
            float hv = (cp == 0) ? h4.x : (cp == 1) ? h4.y : (cp == 2) ? h4.z : h4.w;
            float hk = __shfl_sync(0xFFFFFFFFu, hv, sl);
            const float* wr = sW + kk * DDIM;
            u0 += hk * wr[lane];
            u1 += hk * wr[lane + 32];
            u2 += hk * wr[lane + 64];
            u3 += hk * wr[lane + 96];
        }
    }
    if (active) {
        float acc = tanhf(u0) * attn_b[lane] + tanhf(u1) * attn_b[lane + 32]
                  + tanhf(u2) * attn_b[lane + 64] + tanhf(u3) * attn_b[lane + 96];
#pragma unroll
        for (int o = 16; o; o >>= 1) acc += __shfl_xor_sync(0xFFFFFFFFu, acc, o);
        if (lane == 0) g_sent[slot] = acc;
    }
}

// ---------------------------------------------------------------------------
// fused output kernel: blocks [0,64) = users, [64,320) = entities
// ---------------------------------------------------------------------------
__global__ void __launch_bounds__(DDIM) k_out(const int* __restrict__ ctx,
                       const int* __restrict__ cmask,
                       const int* __restrict__ entity_ids,
                       const float* __restrict__ fc1_W, const float* __restrict__ fc1_b,
                       const float* __restrict__ fc2_W, const float* __restrict__ fc2_b,
                       const float* __restrict__ efc1_W, const float* __restrict__ efc1_b,
                       const float* __restrict__ efc2_W, const float* __restrict__ efc2_b,
                       float* __restrict__ out) {
    __shared__ float xin[DDIM];
    __shared__ float yv[DDIM];
    __shared__ float attn[L_CTX];
    int t = threadIdx.x;

    const float *W1, *b1, *W2, *b2;
    float* dst;

    if (blockIdx.x < B_USERS) {
        int b = blockIdx.x;
        if (t == 0) {
            float mx = -3.4e38f; bool any = false;
            float scl[L_CTX];
            for (int l = 0; l < L_CTX; l++) {
                scl[l] = g_sent[g_slot[ctx[b * L_CTX + l]]];
                if (cmask[b * L_CTX + l]) { any = true; mx = fmaxf(mx, scl[l]); }
            }
            float s = 0.f;
            for (int l = 0; l < L_CTX; l++) {
                float v = cmask[b * L_CTX + l] ? expf(scl[l] - mx) : 0.f;
                attn[l] = v; s += v;
            }
            float inv = any ? 1.f / s : 0.f;
            for (int l = 0; l < L_CTX; l++) attn[l] *= inv;
        }
        __syncthreads();
        // L_CTX = 50 is even: the pair loop covers all l (no tail)
        float r0 = 0.f, r1 = 0.f;
        for (int l = 0; l < L_CTX; l += 2) {
            int s0 = g_slot[ctx[b * L_CTX + l]];
            int s1 = g_slot[ctx[b * L_CTX + l + 1]];
            r0 += attn[l]     * g_kgc[(size_t)s0 * DDIM + t];
            r1 += attn[l + 1] * g_kgc[(size_t)s1 * DDIM + t];
        }
        xin[t] = r0 + r1;
        W1 = fc1_W; b1 = fc1_b; W2 = fc2_W; b2 = fc2_b;
        dst = out + b * DDIM;
    } else {
        int i = blockIdx.x - B_USERS;
        int slot = g_slot[entity_ids[i]];
        xin[t] = g_kgc[(size_t)slot * DDIM + t];
        W1 = efc1_W; b1 = efc1_b; W2 = efc2_W; b2 = efc2_b;
        dst = out + B_USERS * DDIM + i * DDIM;
    }
    __syncthreads();

    float y0 = 0.f, y1 = 0.f, y2 = 0.f, y3 = 0.f;
#pragma unroll 4
    for (int k = 0; k < DDIM; k += 4) {
        y0 += xin[k]     * W1[(k)     * DDIM + t];
        y1 += xin[k + 1] * W1[(k + 1) * DDIM + t];
        y2 += xin[k + 2] * W1[(k + 2) * DDIM + t];
        y3 += xin[k + 3] * W1[(k + 3) * DDIM + t];
    }
    yv[t] = fmaxf(b1[t] + (y0 + y1) + (y2 + y3), 0.f);
    __syncthreads();

    float o0 = 0.f, o1 = 0.f, o2 = 0.f, o3 = 0.f;
#pragma unroll 4
    for (int k = 0; k < DDIM; k += 4) {
        o0 += yv[k]     * W2[(k)     * DDIM + t];
        o1 += yv[k + 1] * W2[(k + 1) * DDIM + t];
        o2 += yv[k + 2] * W2[(k + 2) * DDIM + t];
        o3 += yv[k + 3] * W2[(k + 3) * DDIM + t];
    }
    dst[t] = b2[t] + (o0 + o1) + (o2 + o3);
}

// ---------------------------------------------------------------------------
extern "C" void kernel_launch(void* const* d_in, const int* in_sizes, int n_in,
                              void* d_out, int out_size) {
    const int*   edge_index = (const int*)d_in[0];
    const int*   edge_type  = (const int*)d_in[1];
    const int*   ctx        = (const int*)d_in[2];
    const int*   cmask      = (const int*)d_in[3];
    const int*   entity_ids = (const int*)d_in[4];
    const float* comp       = (const float*)d_in[5];
    const float* basis      = (const float*)d_in[6];
    const float* root       = (const float*)d_in[7];
    const float* bias       = (const float*)d_in[8];
    const float* attn_W     = (const float*)d_in[9];
    const float* attn_b     = (const float*)d_in[10];
    const float* fc1_W      = (const float*)d_in[11];
    const float* fc1_b      = (const float*)d_in[12];
    const float* fc2_W      = (const float*)d_in[13];
    const float* fc2_b      = (const float*)d_in[14];
    const float* efc1_W     = (const float*)d_in[15];
    const float* efc1_b     = (const float*)d_in[16];
    const float* efc2_W     = (const float*)d_in[17];
    const float* efc2_b     = (const float*)d_in[18];
    float* out = (float*)d_out;

    k_setup<<<128, 256>>>();
    k_assign<<<(NCAND + 255) / 256, 256>>>(ctx, entity_ids);
    k_epass<<<(E_EDGES + 255) / 256, 256>>>(edge_index, edge_type);
    k_csort<<<1, 1024>>>();
    k_agg<<<(MMAX * 32) / 256, 256>>>(basis, comp, root, bias);
    k_score<<<MMAX / SC_WARPS, SC_WARPS * 32>>>(attn_W, attn_b);
    k_out<<<B_USERS + NE_ENT, DDIM>>>(ctx, cmask, entity_ids,
                                      fc1_W, fc1_b, fc2_W, fc2_b,
                                      efc1_W, efc1_b, efc2_W, efc2_b, out);
}

// round 12
// speedup vs baseline: 1.1890x; 1.1698x over previous
#include <cuda_runtime.h>
#include <cuda_bf16.h>
#include <math.h>

#define N_ENTITY 64368
#define N_REL    46
#define NBASES   8
#define DDIM     128
#define E_EDGES  600000
#define B_USERS  64
#define L_CTX    50
#define NE_ENT   256

#define NCAND    (B_USERS * L_CTX + NE_ENT)   // 3456 candidate ids
#define MMAX     4096                          // > NCAND

// ---- device-global scratch (allocation forbidden; int atomics only) ----
__device__ int   g_slot[N_ENTITY];         // entity -> compact slot (-1 if unused)
__device__ int   g_ent[MMAX];              // slot -> entity
__device__ int   g_M;                      // number of used slots
__device__ int   g_ne;                     // number of relevant edges
__device__ int2  g_clist[E_EDGES];         // compact unsorted relevant edges {slot, src|rel<<17}
__device__ int   g_hist2[MMAX];            // relevant edges per slot
__device__ int   g_eoff[MMAX + 1];         // slot-sorted edge offsets
__device__ int   g_cur2[MMAX];             // scatter cursors
__device__ int   g_deg2[MMAX * N_REL];     // per-(slot,rel) degree
__device__ int   g_elist[E_EDGES];         // slot-sorted edges: src | (rel<<17)
__device__ __align__(16) float g_kgc[MMAX * DDIM];  // 2 MB compact kg_emb
__device__ float g_sent[MMAX];             // per-slot attention score

// ---------------------------------------------------------------------------
// setup: slot = -1, counters = 0
// ---------------------------------------------------------------------------
__global__ void k_setup() {
    const int stride = gridDim.x * blockDim.x;
    const int tid = blockIdx.x * blockDim.x + threadIdx.x;
    for (int i = tid; i < N_ENTITY; i += stride) g_slot[i] = -1;
    if (tid == 0) { g_M = 0; g_ne = 0; }
}

// ---------------------------------------------------------------------------
// assign compact slots to candidate entities (CAS dedup; order-free).
// claimer zeroes its slot's degree row + hist entry before publishing.
// ---------------------------------------------------------------------------
__global__ void k_assign(const int* __restrict__ ctx, const int* __restrict__ entity_ids) {
    int t = blockIdx.x * blockDim.x + threadIdx.x;
    if (t >= NCAND) return;
    int id = (t < B_USERS * L_CTX) ? ctx[t] : entity_ids[t - B_USERS * L_CTX];
    if (atomicCAS(&g_slot[id], -1, -2) == -1) {
        int s = atomicAdd(&g_M, 1);
        g_ent[s] = id;
        g_hist2[s] = 0;
#pragma unroll
        for (int r = 0; r < N_REL; r++) g_deg2[s * N_REL + r] = 0;
        g_slot[id] = s;                 // publish after deg/hist are zeroed
    }
}

// ---------------------------------------------------------------------------
// SINGLE 600K edge pass: degree + hist atomics, compact append of relevant edges
// ---------------------------------------------------------------------------
__global__ void k_epass(const int* __restrict__ edge_index, const int* __restrict__ edge_type) {
    int e = blockIdx.x * blockDim.x + threadIdx.x;
    if (e >= E_EDGES) return;
    int dst = edge_index[E_EDGES + e];
    int s = g_slot[dst];
    if (s < 0) return;
    int rel = edge_type[e];
    int src = edge_index[e];
    atomicAdd(&g_deg2[s * N_REL + rel], 1);
    atomicAdd(&g_hist2[s], 1);
    int p = atomicAdd(&g_ne, 1);
    g_clist[p] = make_int2(s, src | (rel << 17));   // src < 2^17, rel < 2^6
}

// ---------------------------------------------------------------------------
// scan of 4096 slot bins only (16 KB — within single-block budget)
// ---------------------------------------------------------------------------
__global__ void __launch_bounds__(1024) k_escan() {
    __shared__ int wsum[32];
    int t = threadIdx.x, lane = t & 31, wid = t >> 5;
    int v[4]; int sum = 0;
#pragma unroll
    for (int j = 0; j < 4; j++) { v[j] = g_hist2[t * 4 + j]; sum += v[j]; }
    int s = sum;
#pragma unroll
    for (int o = 1; o < 32; o <<= 1) {
        int a = __shfl_up_sync(0xFFFFFFFFu, s, o);
        if (lane >= o) s += a;
    }
    if (lane == 31) wsum[wid] = s;
    __syncthreads();
    if (wid == 0) {
        int ws = wsum[lane];
#pragma unroll
        for (int o = 1; o < 32; o <<= 1) {
            int a = __shfl_up_sync(0xFFFFFFFFu, ws, o);
            if (lane >= o) ws += a;
        }
        wsum[lane] = ws;
    }
    __syncthreads();
    int base = ((wid > 0) ? wsum[wid - 1] : 0) + s - sum;   // exclusive prefix
#pragma unroll
    for (int j = 0; j < 4; j++) {
        g_eoff[t * 4 + j] = base;
        g_cur2[t * 4 + j] = base;
        base += v[j];
    }
    if (t == 1023) g_eoff[MMAX] = base;
}

// ---------------------------------------------------------------------------
// parallel scatter of the ~32K compact entries into slot-sorted order
// ---------------------------------------------------------------------------
__global__ void k_escatter() {
    int n = g_ne;
    int stride = gridDim.x * blockDim.x;
    for (int i = blockIdx.x * blockDim.x + threadIdx.x; i < n; i += stride) {
        int2 e = g_clist[i];
        int pos = atomicAdd(&g_cur2[e.x], 1);
        g_elist[pos] = e.y;
    }
}

// ---------------------------------------------------------------------------
// aggregation: warp per needed slot; gather basis rows directly.
// kg = root + bias + sum_edges norm * sum_b comp[rel,b] * basis[b][src]
// ---------------------------------------------------------------------------
__global__ void __launch_bounds__(256) k_agg(const float* __restrict__ basis,
                                             const float* __restrict__ comp,
                                             const float* __restrict__ root,
                                             const float* __restrict__ bias) {
    __shared__ float s_comp[N_REL * NBASES];
    for (int i = threadIdx.x; i < N_REL * NBASES; i += blockDim.x) s_comp[i] = comp[i];
    __syncthreads();

    int slot = (blockIdx.x * blockDim.x + threadIdx.x) >> 5;
    int lane = threadIdx.x & 31;
    if (slot >= g_M) return;

    int ent = g_ent[slot];
    float4 acc = reinterpret_cast<const float4*>(root)[(size_t)ent * 32 + lane];
    float4 bv  = reinterpret_cast<const float4*>(bias)[lane];
    acc.x += bv.x; acc.y += bv.y; acc.z += bv.z; acc.w += bv.w;

    int n0 = g_eoff[slot], n1 = g_eoff[slot + 1];
    for (int i = n0; i < n1; i++) {
        int packed = g_elist[i];                 // warp-broadcast load
        int src = packed & 0x1FFFF;
        int rel = packed >> 17;
        float norm = 1.0f / (float)max(g_deg2[slot * N_REL + rel], 1);
        const float* c = s_comp + rel * NBASES;
        const float4* bp = reinterpret_cast<const float4*>(basis) + (size_t)src * 32 + lane;
        float4 br[NBASES];
#pragma unroll
        for (int b = 0; b < NBASES; b++) br[b] = bp[(size_t)b * (N_ENTITY * 32)];
        float4 m;
        m.x = c[0] * br[0].x; m.y = c[0] * br[0].y; m.z = c[0] * br[0].z; m.w = c[0] * br[0].w;
#pragma unroll
        for (int b = 1; b < NBASES; b++) {
            float cb = c[b];
            m.x += cb * br[b].x; m.y += cb * br[b].y; m.z += cb * br[b].z; m.w += cb * br[b].w;
        }
        acc.x += norm * m.x; acc.y += norm * m.y; acc.z += norm * m.z; acc.w += norm * m.w;
    }
    reinterpret_cast<float4*>(g_kgc)[(size_t)slot * 32 + lane] = acc;
}

// ---------------------------------------------------------------------------
// per-slot attention score; attn_W staged through smem in 32-row tiles.
// block = 8 warps, each warp owns one slot.
// ---------------------------------------------------------------------------
#define SC_WARPS 8
__global__ void __launch_bounds__(SC_WARPS * 32) k_score(const float* __restrict__ attn_W,
                                                         const float* __restrict__ attn_b) {
    __shared__ float sW[32 * DDIM];     // 16 KB tile
    int t = threadIdx.x;
    int lane = t & 31, wid = t >> 5;
    int slot = blockIdx.x * SC_WARPS + wid;
    bool active = slot < g_M;

    float4 h4 = make_float4(0.f, 0.f, 0.f, 0.f);
    if (active)
        h4 = reinterpret_cast<const float4*>(g_kgc + (size_t)slot * DDIM)[lane];

    float u0 = 0.f, u1 = 0.f, u2 = 0.f, u3 = 0.f;
#pragma unroll
    for (int tile = 0; tile < DDIM / 32; tile++) {
        __syncthreads();
        for (int i = t; i < 32 * DDIM; i += SC_WARPS * 32)
            sW[i] = attn_W[tile * 32 * DDIM + i];
        __syncthreads();
#pragma unroll 4
        for (int kk = 0; kk < 32; kk++) {
            int k = tile * 32 + kk;
            int sl = k >> 2, cp = k & 3;
            float hv = (cp == 0) ? h4.x : (cp == 1) ? h4.y : (cp == 2) ? h4.z : h4.w;
            float hk = __shfl_sync(0xFFFFFFFFu, hv, sl);
            const float* wr = sW + kk * DDIM;
            u0 += hk * wr[lane];
            u1 += hk * wr[lane + 32];
            u2 += hk * wr[lane + 64];
            u3 += hk * wr[lane + 96];
        }
    }
    if (active) {
        float acc = tanhf(u0) * attn_b[lane] + tanhf(u1) * attn_b[lane + 32]
                  + tanhf(u2) * attn_b[lane + 64] + tanhf(u3) * attn_b[lane + 96];
#pragma unroll
        for (int o = 16; o; o >>= 1) acc += __shfl_xor_sync(0xFFFFFFFFu, acc, o);
        if (lane == 0) g_sent[slot] = acc;
    }
}

// ---------------------------------------------------------------------------
// fused output kernel: blocks [0,64) = users, [64,320) = entities
// ---------------------------------------------------------------------------
__global__ void __launch_bounds__(DDIM) k_out(const int* __restrict__ ctx,
                       const int* __restrict__ cmask,
                       const int* __restrict__ entity_ids,
                       const float* __restrict__ fc1_W, const float* __restrict__ fc1_b,
                       const float* __restrict__ fc2_W, const float* __restrict__ fc2_b,
                       const float* __restrict__ efc1_W, const float* __restrict__ efc1_b,
                       const float* __restrict__ efc2_W, const float* __restrict__ efc2_b,
                       float* __restrict__ out) {
    __shared__ float xin[DDIM];
    __shared__ float yv[DDIM];
    __shared__ float attn[L_CTX];
    int t = threadIdx.x;

    const float *W1, *b1, *W2, *b2;
    float* dst;

    if (blockIdx.x < B_USERS) {
        int b = blockIdx.x;
        if (t == 0) {
            float mx = -3.4e38f; bool any = false;
            float scl[L_CTX];
            for (int l = 0; l < L_CTX; l++) {
                scl[l] = g_sent[g_slot[ctx[b * L_CTX + l]]];
                if (cmask[b * L_CTX + l]) { any = true; mx = fmaxf(mx, scl[l]); }
            }
            float s = 0.f;
            for (int l = 0; l < L_CTX; l++) {
                float v = cmask[b * L_CTX + l] ? expf(scl[l] - mx) : 0.f;
                attn[l] = v; s += v;
            }
            float inv = any ? 1.f / s : 0.f;
            for (int l = 0; l < L_CTX; l++) attn[l] *= inv;
        }
        __syncthreads();
        // L_CTX = 50 is even: the pair loop covers all l (no tail)
        float r0 = 0.f, r1 = 0.f;
        for (int l = 0; l < L_CTX; l += 2) {
            int s0 = g_slot[ctx[b * L_CTX + l]];
            int s1 = g_slot[ctx[b * L_CTX + l + 1]];
            r0 += attn[l]     * g_kgc[(size_t)s0 * DDIM + t];
            r1 += attn[l + 1] * g_kgc[(size_t)s1 * DDIM + t];
        }
        xin[t] = r0 + r1;
        W1 = fc1_W; b1 = fc1_b; W2 = fc2_W; b2 = fc2_b;
        dst = out + b * DDIM;
    } else {
        int i = blockIdx.x - B_USERS;
        int slot = g_slot[entity_ids[i]];
        xin[t] = g_kgc[(size_t)slot * DDIM + t];
        W1 = efc1_W; b1 = efc1_b; W2 = efc2_W; b2 = efc2_b;
        dst = out + B_USERS * DDIM + i * DDIM;
    }
    __syncthreads();

    float y0 = 0.f, y1 = 0.f, y2 = 0.f, y3 = 0.f;
#pragma unroll 4
    for (int k = 0; k < DDIM; k += 4) {
        y0 += xin[k]     * W1[(k)     * DDIM + t];
        y1 += xin[k + 1] * W1[(k + 1) * DDIM + t];
        y2 += xin[k + 2] * W1[(k + 2) * DDIM + t];
        y3 += xin[k + 3] * W1[(k + 3) * DDIM + t];
    }
    yv[t] = fmaxf(b1[t] + (y0 + y1) + (y2 + y3), 0.f);
    __syncthreads();

    float o0 = 0.f, o1 = 0.f, o2 = 0.f, o3 = 0.f;
#pragma unroll 4
    for (int k = 0; k < DDIM; k += 4) {
        o0 += yv[k]     * W2[(k)     * DDIM + t];
        o1 += yv[k + 1] * W2[(k + 1) * DDIM + t];
        o2 += yv[k + 2] * W2[(k + 2) * DDIM + t];
        o3 += yv[k + 3] * W2[(k + 3) * DDIM + t];
    }
    dst[t] = b2[t] + (o0 + o1) + (o2 + o3);
}

// ---------------------------------------------------------------------------
extern "C" void kernel_launch(void* const* d_in, const int* in_sizes, int n_in,
                              void* d_out, int out_size) {
    const int*   edge_index = (const int*)d_in[0];
    const int*   edge_type  = (const int*)d_in[1];
    const int*   ctx        = (const int*)d_in[2];
    const int*   cmask      = (const int*)d_in[3];
    const int*   entity_ids = (const int*)d_in[4];
    const float* comp       = (const float*)d_in[5];
    const float* basis      = (const float*)d_in[6];
    const float* root       = (const float*)d_in[7];
    const float* bias       = (const float*)d_in[8];
    const float* attn_W     = (const float*)d_in[9];
    const float* attn_b     = (const float*)d_in[10];
    const float* fc1_W      = (const float*)d_in[11];
    const float* fc1_b      = (const float*)d_in[12];
    const float* fc2_W      = (const float*)d_in[13];
    const float* fc2_b      = (const float*)d_in[14];
    const float* efc1_W     = (const float*)d_in[15];
    const float* efc1_b     = (const float*)d_in[16];
    const float* efc2_W     = (const float*)d_in[17];
    const float* efc2_b     = (const float*)d_in[18];
    float* out = (float*)d_out;

    k_setup<<<128, 256>>>();
    k_assign<<<(NCAND + 255) / 256, 256>>>(ctx, entity_ids);
    k_epass<<<(E_EDGES + 255) / 256, 256>>>(edge_index, edge_type);
    k_escan<<<1, 1024>>>();
    k_escatter<<<64, 256>>>();
    k_agg<<<(MMAX * 32) / 256, 256>>>(basis, comp, root, bias);
    k_score<<<MMAX / SC_WARPS, SC_WARPS * 32>>>(attn_W, attn_b);
    k_out<<<B_USERS + NE_ENT, DDIM>>>(ctx, cmask, entity_ids,
                                      fc1_W, fc1_b, fc2_W, fc2_b,
                                      efc1_W, efc1_b, efc2_W, efc2_b, out);
}

// round 13
// speedup vs baseline: 1.1971x; 1.0068x over previous
#include <cuda_runtime.h>
#include <cuda_bf16.h>
#include <math.h>

#define N_ENTITY 64368
#define N_REL    46
#define NBASES   8
#define DDIM     128
#define E_EDGES  600000
#define B_USERS  64
#define L_CTX    50
#define NE_ENT   256

#define NCAND    (B_USERS * L_CTX + NE_ENT)   // 3456 candidate ids
#define MMAX     4096                          // > NCAND; slot fits in 12 bits

// ---- device-global scratch (allocation forbidden; int atomics only) ----
__device__ int   g_slot[N_ENTITY];         // entity -> compact slot (-1 if unused)
__device__ int   g_ent[MMAX];              // slot -> entity
__device__ int   g_M;                      // number of used slots
__device__ int   g_ne;                     // number of relevant edges
__device__ int2  g_clist[E_EDGES];         // {slot | rank<<12, src|rel<<17} unsorted
__device__ int   g_hist2[MMAX];            // relevant edges per slot (atomic = rank source)
__device__ int   g_eoff[MMAX + 1];         // slot-sorted edge offsets
__device__ int   g_deg2[MMAX * N_REL];     // per-(slot,rel) degree
__device__ int   g_elist[E_EDGES];         // slot-sorted edges: src | (rel<<17)
__device__ __align__(16) float g_kgc[MMAX * DDIM];  // 2 MB compact kg_emb
__device__ float g_sent[MMAX];             // per-slot attention score

// ---------------------------------------------------------------------------
// setup: slot = -1, counters = 0
// ---------------------------------------------------------------------------
__global__ void k_setup() {
    const int stride = gridDim.x * blockDim.x;
    const int tid = blockIdx.x * blockDim.x + threadIdx.x;
    for (int i = tid; i < N_ENTITY; i += stride) g_slot[i] = -1;
    if (tid == 0) { g_M = 0; g_ne = 0; }
}

// ---------------------------------------------------------------------------
// assign compact slots to candidate entities (CAS dedup; order-free).
// claimer zeroes its slot's degree row + hist entry before publishing.
// ---------------------------------------------------------------------------
__global__ void k_assign(const int* __restrict__ ctx, const int* __restrict__ entity_ids) {
    int t = blockIdx.x * blockDim.x + threadIdx.x;
    if (t >= NCAND) return;
    int id = (t < B_USERS * L_CTX) ? ctx[t] : entity_ids[t - B_USERS * L_CTX];
    if (atomicCAS(&g_slot[id], -1, -2) == -1) {
        int s = atomicAdd(&g_M, 1);
        g_ent[s] = id;
        g_hist2[s] = 0;
#pragma unroll
        for (int r = 0; r < N_REL; r++) g_deg2[s * N_REL + r] = 0;
        g_slot[id] = s;                 // publish after deg/hist are zeroed
    }
}

// ---------------------------------------------------------------------------
// SINGLE 600K edge pass. Per relevant edge:
//   deg atomic; rank = per-slot hist atomic (gives final position later);
//   compact append via BLOCK-aggregated counter (one global atomic per block).
// ---------------------------------------------------------------------------
__global__ void __launch_bounds__(256) k_epass(const int* __restrict__ edge_index,
                                               const int* __restrict__ edge_type) {
    __shared__ int s_cnt, s_base;
    if (threadIdx.x == 0) s_cnt = 0;
    __syncthreads();

    int e = blockIdx.x * blockDim.x + threadIdx.x;
    int s = -1, payload = 0, rank = 0, local = 0;
    if (e < E_EDGES) {
        int dst = edge_index[E_EDGES + e];
        s = g_slot[dst];
        if (s >= 0) {
            int rel = edge_type[e];
            int src = edge_index[e];
            atomicAdd(&g_deg2[s * N_REL + rel], 1);
            rank = atomicAdd(&g_hist2[s], 1);       // rank within slot (free position!)
            payload = src | (rel << 17);            // src < 2^17, rel < 2^6
            local = atomicAdd(&s_cnt, 1);           // smem atomic (cheap)
        }
    }
    __syncthreads();
    if (threadIdx.x == 0) s_base = atomicAdd(&g_ne, s_cnt);   // ONE global atomic/block
    __syncthreads();
    if (s >= 0)
        g_clist[s_base + local] =
            make_int2((int)((unsigned)s | ((unsigned)rank << 12)), payload);
}

// ---------------------------------------------------------------------------
// scan of 4096 slot bins (16 KB — within single-block budget)
// ---------------------------------------------------------------------------
__global__ void __launch_bounds__(1024) k_escan() {
    __shared__ int wsum[32];
    int t = threadIdx.x, lane = t & 31, wid = t >> 5;
    int v[4]; int sum = 0;
#pragma unroll
    for (int j = 0; j < 4; j++) { v[j] = g_hist2[t * 4 + j]; sum += v[j]; }
    int s = sum;
#pragma unroll
    for (int o = 1; o < 32; o <<= 1) {
        int a = __shfl_up_sync(0xFFFFFFFFu, s, o);
        if (lane >= o) s += a;
    }
    if (lane == 31) wsum[wid] = s;
    __syncthreads();
    if (wid == 0) {
        int ws = wsum[lane];
#pragma unroll
        for (int o = 1; o < 32; o <<= 1) {
            int a = __shfl_up_sync(0xFFFFFFFFu, ws, o);
            if (lane >= o) ws += a;
        }
        wsum[lane] = ws;
    }
    __syncthreads();
    int base = ((wid > 0) ? wsum[wid - 1] : 0) + s - sum;   // exclusive prefix
#pragma unroll
    for (int j = 0; j < 4; j++) { g_eoff[t * 4 + j] = base; base += v[j]; }
    if (t == 1023) g_eoff[MMAX] = base;
}

// ---------------------------------------------------------------------------
// deterministic parallel scatter: pos = eoff[slot] + rank (NO atomics)
// ---------------------------------------------------------------------------
__global__ void k_escatter() {
    int n = g_ne;
    int stride = gridDim.x * blockDim.x;
    for (int i = blockIdx.x * blockDim.x + threadIdx.x; i < n; i += stride) {
        int2 c = g_clist[i];
        unsigned x = (unsigned)c.x;
        int slot = x & 0xFFF;
        int rank = (int)(x >> 12);
        g_elist[g_eoff[slot] + rank] = c.y;
    }
}

// ---------------------------------------------------------------------------
// FUSED aggregation + attention score. Warp per slot.
// Phase 1: kg = root + bias + sum_edges norm * sum_b comp[rel,b]*basis[b][src]
// Phase 2: score = sum_d tanh((kg @ W)[d]) * ab[d]  -- kg still in registers
// ---------------------------------------------------------------------------
__global__ void __launch_bounds__(256) k_aggsc(const float* __restrict__ basis,
                                               const float* __restrict__ comp,
                                               const float* __restrict__ root,
                                               const float* __restrict__ bias,
                                               const float* __restrict__ attn_W,
                                               const float* __restrict__ attn_b) {
    __shared__ float s_comp[N_REL * NBASES];
    __shared__ float sW[32 * DDIM];     // 16 KB tile
    int t = threadIdx.x;
    for (int i = t; i < N_REL * NBASES; i += blockDim.x) s_comp[i] = comp[i];
    __syncthreads();

    int slot = (blockIdx.x * blockDim.x + t) >> 5;
    int lane = t & 31;
    bool active = slot < g_M;

    float4 acc = make_float4(0.f, 0.f, 0.f, 0.f);
    if (active) {
        int ent = g_ent[slot];
        acc = reinterpret_cast<const float4*>(root)[(size_t)ent * 32 + lane];
        float4 bv = reinterpret_cast<const float4*>(bias)[lane];
        acc.x += bv.x; acc.y += bv.y; acc.z += bv.z; acc.w += bv.w;

        int n0 = g_eoff[slot], n1 = g_eoff[slot + 1];
        for (int i = n0; i < n1; i++) {
            int packed = g_elist[i];                 // warp-broadcast load
            int src = packed & 0x1FFFF;
            int rel = packed >> 17;
            float norm = 1.0f / (float)max(g_deg2[slot * N_REL + rel], 1);
            const float* c = s_comp + rel * NBASES;
            const float4* bp = reinterpret_cast<const float4*>(basis) + (size_t)src * 32 + lane;
            float4 br[NBASES];
#pragma unroll
            for (int b = 0; b < NBASES; b++) br[b] = bp[(size_t)b * (N_ENTITY * 32)];
            float4 m;
            m.x = c[0] * br[0].x; m.y = c[0] * br[0].y; m.z = c[0] * br[0].z; m.w = c[0] * br[0].w;
#pragma unroll
            for (int b = 1; b < NBASES; b++) {
                float cb = c[b];
                m.x += cb * br[b].x; m.y += cb * br[b].y; m.z += cb * br[b].z; m.w += cb * br[b].w;
            }
            acc.x += norm * m.x; acc.y += norm * m.y; acc.z += norm * m.z; acc.w += norm * m.w;
        }
        reinterpret_cast<float4*>(g_kgc)[(size_t)slot * 32 + lane] = acc;
    }

    // ---- phase 2: score, using acc (the embedding row) still in registers ----
    float u0 = 0.f, u1 = 0.f, u2 = 0.f, u3 = 0.f;
#pragma unroll
    for (int tile = 0; tile < DDIM / 32; tile++) {
        __syncthreads();
        for (int i = t; i < 32 * DDIM; i += 256)
            sW[i] = attn_W[tile * 32 * DDIM + i];
        __syncthreads();
#pragma unroll 4
        for (int kk = 0; kk < 32; kk++) {
            int k = tile * 32 + kk;
            int sl = k >> 2, cp = k & 3;
            float hv = (cp == 0) ? acc.x : (cp == 1) ? acc.y : (cp == 2) ? acc.z : acc.w;
            float hk = __shfl_sync(0xFFFFFFFFu, hv, sl);
            const float* wr = sW + kk * DDIM;
            u0 += hk * wr[lane];
            u1 += hk * wr[lane + 32];
            u2 += hk * wr[lane + 64];
            u3 += hk * wr[lane + 96];
        }
    }
    if (active) {
        float sc = tanhf(u0) * attn_b[lane] + tanhf(u1) * attn_b[lane + 32]
                 + tanhf(u2) * attn_b[lane + 64] + tanhf(u3) * attn_b[lane + 96];
#pragma unroll
        for (int o = 16; o; o >>= 1) sc += __shfl_xor_sync(0xFFFFFFFFu, sc, o);
        if (lane == 0) g_sent[slot] = sc;
    }
}

// ---------------------------------------------------------------------------
// fused output kernel: blocks [0,64) = users, [64,320) = entities
// ---------------------------------------------------------------------------
__global__ void __launch_bounds__(DDIM) k_out(const int* __restrict__ ctx,
                       const int* __restrict__ cmask,
                       const int* __restrict__ entity_ids,
                       const float* __restrict__ fc1_W, const float* __restrict__ fc1_b,
                       const float* __restrict__ fc2_W, const float* __restrict__ fc2_b,
                       const float* __restrict__ efc1_W, const float* __restrict__ efc1_b,
                       const float* __restrict__ efc2_W, const float* __restrict__ efc2_b,
                       float* __restrict__ out) {
    __shared__ float xin[DDIM];
    __shared__ float yv[DDIM];
    __shared__ float attn[L_CTX];
    int t = threadIdx.x;

    const float *W1, *b1, *W2, *b2;
    float* dst;

    if (blockIdx.x < B_USERS) {
        int b = blockIdx.x;
        if (t == 0) {
            float mx = -3.4e38f; bool any = false;
            float scl[L_CTX];
            for (int l = 0; l < L_CTX; l++) {
                scl[l] = g_sent[g_slot[ctx[b * L_CTX + l]]];
                if (cmask[b * L_CTX + l]) { any = true; mx = fmaxf(mx, scl[l]); }
            }
            float s = 0.f;
            for (int l = 0; l < L_CTX; l++) {
                float v = cmask[b * L_CTX + l] ? expf(scl[l] - mx) : 0.f;
                attn[l] = v; s += v;
            }
            float inv = any ? 1.f / s : 0.f;
            for (int l = 0; l < L_CTX; l++) attn[l] *= inv;
        }
        __syncthreads();
        // L_CTX = 50 is even: the pair loop covers all l (no tail)
        float r0 = 0.f, r1 = 0.f;
        for (int l = 0; l < L_CTX; l += 2) {
            int s0 = g_slot[ctx[b * L_CTX + l]];
            int s1 = g_slot[ctx[b * L_CTX + l + 1]];
            r0 += attn[l]     * g_kgc[(size_t)s0 * DDIM + t];
            r1 += attn[l + 1] * g_kgc[(size_t)s1 * DDIM + t];
        }
        xin[t] = r0 + r1;
        W1 = fc1_W; b1 = fc1_b; W2 = fc2_W; b2 = fc2_b;
        dst = out + b * DDIM;
    } else {
        int i = blockIdx.x - B_USERS;
        int slot = g_slot[entity_ids[i]];
        xin[t] = g_kgc[(size_t)slot * DDIM + t];
        W1 = efc1_W; b1 = efc1_b; W2 = efc2_W; b2 = efc2_b;
        dst = out + B_USERS * DDIM + i * DDIM;
    }
    __syncthreads();

    float y0 = 0.f, y1 = 0.f, y2 = 0.f, y3 = 0.f;
#pragma unroll 4
    for (int k = 0; k < DDIM; k += 4) {
        y0 += xin[k]     * W1[(k)     * DDIM + t];
        y1 += xin[k + 1] * W1[(k + 1) * DDIM + t];
        y2 += xin[k + 2] * W1[(k + 2) * DDIM + t];
        y3 += xin[k + 3] * W1[(k + 3) * DDIM + t];
    }
    yv[t] = fmaxf(b1[t] + (y0 + y1) + (y2 + y3), 0.f);
    __syncthreads();

    float o0 = 0.f, o1 = 0.f, o2 = 0.f, o3 = 0.f;
#pragma unroll 4
    for (int k = 0; k < DDIM; k += 4) {
        o0 += yv[k]     * W2[(k)     * DDIM + t];
        o1 += yv[k + 1] * W2[(k + 1) * DDIM + t];
        o2 += yv[k + 2] * W2[(k + 2) * DDIM + t];
        o3 += yv[k + 3] * W2[(k + 3) * DDIM + t];
    }
    dst[t] = b2[t] + (o0 + o1) + (o2 + o3);
}

// ---------------------------------------------------------------------------
extern "C" void kernel_launch(void* const* d_in, const int* in_sizes, int n_in,
                              void* d_out, int out_size) {
    const int*   edge_index = (const int*)d_in[0];
    const int*   edge_type  = (const int*)d_in[1];
    const int*   ctx        = (const int*)d_in[2];
    const int*   cmask      = (const int*)d_in[3];
    const int*   entity_ids = (const int*)d_in[4];
    const float* comp       = (const float*)d_in[5];
    const float* basis      = (const float*)d_in[6];
    const float* root       = (const float*)d_in[7];
    const float* bias       = (const float*)d_in[8];
    const float* attn_W     = (const float*)d_in[9];
    const float* attn_b     = (const float*)d_in[10];
    const float* fc1_W      = (const float*)d_in[11];
    const float* fc1_b      = (const float*)d_in[12];
    const float* fc2_W      = (const float*)d_in[13];
    const float* fc2_b      = (const float*)d_in[14];
    const float* efc1_W     = (const float*)d_in[15];
    const float* efc1_b     = (const float*)d_in[16];
    const float* efc2_W     = (const float*)d_in[17];
    const float* efc2_b     = (const float*)d_in[18];
    float* out = (float*)d_out;

    k_setup<<<128, 256>>>();
    k_assign<<<(NCAND + 255) / 256, 256>>>(ctx, entity_ids);
    k_epass<<<(E_EDGES + 255) / 256, 256>>>(edge_index, edge_type);
    k_escan<<<1, 1024>>>();
    k_escatter<<<64, 256>>>();
    k_aggsc<<<(MMAX * 32) / 256, 256>>>(basis, comp, root, bias, attn_W, attn_b);
    k_out<<<B_USERS + NE_ENT, DDIM>>>(ctx, cmask, entity_ids,
                                      fc1_W, fc1_b, fc2_W, fc2_b,
                                      efc1_W, efc1_b, efc2_W, efc2_b, out);
}